// round 14
// baseline (speedup 1.0000x reference)
#include <cuda_runtime.h>

#define N_AGENTS 64
#define N_EDGES  4032
#define D_NODE   16
#define HDIM     64
#define D_OUT    16
#define BATCH    128

// ---------------------------------------------------------------------------
// f32x2 packed-FMA helpers (sm_103a FFMA2 path; ptxas only emits via PTX)
// ---------------------------------------------------------------------------
__device__ __forceinline__ unsigned long long pack_f32x2(float lo, float hi) {
    unsigned long long r;
    asm("mov.b64 %0, {%1, %2};" : "=l"(r) : "f"(lo), "f"(hi));
    return r;
}
#define FMA_F32X2(d, a, b, c) \
    asm("fma.rn.f32x2 %0, %1, %2, %3;" : "=l"(d) : "l"(a), "l"(b), "l"(c))
#define UNPACK_F32X2(lo, hi, in) \
    asm("mov.b64 {%0, %1}, %2;" : "=f"(lo), "=f"(hi) : "l"(in))

// Per-node first-layer projections for both edge encoders.
// Layout: [b][n][enc*64 + h]  (128 floats per node) -> 4 MB each.
__device__ float g_PT[BATCH * N_AGENTS * 2 * HDIM];  // sender-half proj
__device__ float g_PB[BATCH * N_AGENTS * 2 * HDIM];  // receiver-half proj + b1

// ---------------------------------------------------------------------------
// Prepass: PT[b,n,enc,h] = sum_k x[b,n,k] * W1[enc][k][h]
//          PB[b,n,enc,h] = sum_k x[b,n,k] * W1[enc][16+k][h] + b1[enc][h]
// Grid: BATCH*4 blocks, 128 threads; each block handles 16 nodes of one batch.
// ---------------------------------------------------------------------------
__global__ void __launch_bounds__(128) prepass_kernel(
    const float* __restrict__ x,
    const float* __restrict__ e0_w1, const float* __restrict__ e0_b1,
    const float* __restrict__ e1_w1, const float* __restrict__ e1_b1)
{
    __shared__ float w1s[2][32][64];   // 16 KB
    __shared__ float b1s[2][64];
    __shared__ float xs[16][16];

    const int t = threadIdx.x;
    for (int i = t; i < 32 * 64; i += 128) {
        w1s[0][i >> 6][i & 63] = e0_w1[i];
        w1s[1][i >> 6][i & 63] = e1_w1[i];
    }
    if (t < 64) { b1s[0][t] = e0_b1[t]; b1s[1][t] = e1_b1[t]; }

    const int b  = blockIdx.x >> 2;
    const int n0 = (blockIdx.x & 3) * 16;
    for (int i = t; i < 256; i += 128)
        xs[i >> 4][i & 15] = x[(b * N_AGENTS + n0 + (i >> 4)) * D_NODE + (i & 15)];
    __syncthreads();

    const int enc = t >> 6;
    const int h   = t & 63;
    for (int nn = 0; nn < 16; nn++) {
        float pt = 0.f;
        float pb = b1s[enc][h];
        #pragma unroll
        for (int k = 0; k < 16; k++) {
            const float xv = xs[nn][k];
            pt += xv * w1s[enc][k][h];
            pb += xv * w1s[enc][16 + k][h];
        }
        const int n = n0 + nn;
        g_PT[(b * N_AGENTS + n) * 128 + t] = pt;
        g_PB[(b * N_AGENTS + n) * 128 + t] = pb;
    }
}

// ---------------------------------------------------------------------------
// Main fused kernel: one CTA per (batch b, receiver PAIR {r0=2p, r1=2p+1}).
// Loop over ALL 64 senders s (self-edge contribution killed via tw=0, exact
// because relu output is finite and multiplied by 0).
//   h1[rv][col] = relu(PT[b,s,col] + PB[b,r_rv,col]),  col = enc*64+h
//   dot[rv,enc,h] = h1[rv][enc*64 : enc*64+64] . W2[enc][:,h]
//   acc[rv,enc,h] += tw[rv][s][enc] * relu(dot + b2[enc][h])
// Thread t: rv = t>>6, enc = (t>>5)&1, hbase = t&31.
// Each thread owns W2 columns hbase and hbase+32 (packed f32x2, 128 regs)
// and uses fma.rn.f32x2 so one instr = 2 MACs.
// Edge index for (s -> r): e = s*63 + (r < s ? r : r-1)   [np.where row-major]
// ---------------------------------------------------------------------------
__global__ void __launch_bounds__(128) graphconv_main_kernel(
    const float* __restrict__ x,
    const float* __restrict__ edge_types,
    const float* __restrict__ e0_w2, const float* __restrict__ e0_b2,
    const float* __restrict__ e1_w2, const float* __restrict__ e1_b2,
    const float* __restrict__ nd_w1, const float* __restrict__ nd_b1,
    const float* __restrict__ nd_w2, const float* __restrict__ nd_b2,
    float* __restrict__ out)
{
    const int t     = threadIdx.x;
    const int rv    = t >> 6;          // which receiver of the pair
    const int enc   = (t >> 5) & 1;    // encoder
    const int hbase = t & 31;          // columns hbase, hbase+32
    const int b     = blockIdx.x >> 5;
    const int pair  = blockIdx.x & 31;
    const int r0    = pair * 2;

    __shared__ __align__(16) float h1s[2][2][128];  // [buf][rv][col]
    __shared__ float pbs[2][128];                   // PB rows for r0, r1
    __shared__ float tws[2][64][2];                 // [rv][sender][enc]
    __shared__ float xs[2][16];                     // node_states rows
    __shared__ float accs[2][2][64];                // [rv][enc][h]
    __shared__ float hds[2][64];

    // --- per-thread W2 columns (hbase, hbase+32), packed as f32x2 pairs ---
    const float* __restrict__ w2g = (enc == 0) ? e0_w2 : e1_w2;
    unsigned long long wp0[32], wp1[32];
    #pragma unroll
    for (int j = 0; j < 32; j++) {
        wp0[j] = pack_f32x2(w2g[(2 * j) * 64 + hbase],      w2g[(2 * j + 1) * 64 + hbase]);
        wp1[j] = pack_f32x2(w2g[(2 * j) * 64 + hbase + 32], w2g[(2 * j + 1) * 64 + hbase + 32]);
    }
    const float* __restrict__ b2g = (enc == 0) ? e0_b2 : e1_b2;
    const float bias0 = b2g[hbase];
    const float bias1 = b2g[hbase + 32];

    // --- staging loads (each smem slot written by exactly one thread) ---
    pbs[0][t] = g_PB[(b * N_AGENTS + r0) * 128 + t];
    pbs[1][t] = g_PB[(b * N_AGENTS + r0 + 1) * 128 + t];

    // type weights: 256 values, 2 per thread. tw=0 for self edge.
    for (int i = t; i < 256; i += 128) {
        const int trv = i >> 7;
        const int s   = (i >> 1) & 63;
        const int te  = i & 1;
        const int r   = r0 + trv;
        float v = 0.f;
        if (s != r) {
            const int e = s * 63 + (r < s ? r : r - 1);
            v = edge_types[((long)b * N_EDGES + e) * 3 + 1 + te];
        }
        tws[trv][s][te] = v;
    }
    if (t < 32) xs[t >> 4][t & 15] = x[(b * N_AGENTS + r0 + (t >> 4)) * D_NODE + (t & 15)];

    // per-thread PB values for producer phase
    __syncthreads();
    const float pb0 = pbs[0][t];
    const float pb1 = pbs[1][t];

    float acc0 = 0.f, acc1 = 0.f;
    float ptv = g_PT[(b * N_AGENTS + 0) * 128 + t];   // prefetch sender 0

    for (int s = 0; s < 64; s++) {
        const int buf = s & 1;
        // producer: both receivers' h1 for column t
        float a0 = ptv + pb0;
        float a1 = ptv + pb1;
        h1s[buf][0][t] = a0 > 0.f ? a0 : 0.f;
        h1s[buf][1][t] = a1 > 0.f ? a1 : 0.f;
        if (s + 1 < 64)
            ptv = g_PT[(b * N_AGENTS + s + 1) * 128 + t];
        __syncthreads();

        // consumer: dot of h1s[buf][rv][enc*64 .. +64] with 2 weight columns
        const ulonglong2* __restrict__ hv =
            (const ulonglong2*)&h1s[buf][rv][enc * 64];
        unsigned long long d0 = 0ULL, d1 = 0ULL;
        #pragma unroll
        for (int j4 = 0; j4 < 16; j4++) {
            const ulonglong2 p = hv[j4];
            FMA_F32X2(d0, p.x, wp0[2 * j4],     d0);
            FMA_F32X2(d0, p.y, wp0[2 * j4 + 1], d0);
            FMA_F32X2(d1, p.x, wp1[2 * j4],     d1);
            FMA_F32X2(d1, p.y, wp1[2 * j4 + 1], d1);
        }
        float l0, u0, l1, u1;
        UNPACK_F32X2(l0, u0, d0);
        UNPACK_F32X2(l1, u1, d1);
        const float tw = tws[rv][s][enc];
        float eo0 = l0 + u0 + bias0;
        float eo1 = l1 + u1 + bias1;
        eo0 = eo0 > 0.f ? eo0 : 0.f;
        eo1 = eo1 > 0.f ? eo1 : 0.f;
        acc0 = fmaf(tw, eo0, acc0);
        acc1 = fmaf(tw, eo1, acc1);
    }

    accs[rv][enc][hbase]      = acc0;
    accs[rv][enc][hbase + 32] = acc1;
    __syncthreads();

    // --- decoder layer 1: hd[rv][hcol] = relu(b1 + [x, msg] @ nd_w1) ---
    {
        const int drv  = t >> 6;
        const int hcol = t & 63;
        float hd = nd_b1[hcol];
        #pragma unroll
        for (int k = 0; k < 16; k++)
            hd = fmaf(xs[drv][k], nd_w1[k * 64 + hcol], hd);
        #pragma unroll
        for (int k = 0; k < 64; k++) {
            const float m = accs[drv][0][k] + accs[drv][1][k];
            hd = fmaf(m, nd_w1[(16 + k) * 64 + hcol], hd);
        }
        hds[drv][hcol] = hd > 0.f ? hd : 0.f;
    }
    __syncthreads();

    // --- decoder layer 2: out[rv][o] = relu(b2 + hd @ nd_w2) ---
    if (t < 32) {
        const int orv = t >> 4;
        const int o   = t & 15;
        float v = nd_b2[o];
        #pragma unroll
        for (int j = 0; j < 64; j++)
            v = fmaf(hds[orv][j], nd_w2[j * 16 + o], v);
        out[(b * N_AGENTS + r0 + orv) * D_OUT + o] = v > 0.f ? v : 0.f;
    }
}

// ---------------------------------------------------------------------------
extern "C" void kernel_launch(void* const* d_in, const int* in_sizes, int n_in,
                              void* d_out, int out_size)
{
    const float* node_states = (const float*)d_in[0];
    const float* edge_types  = (const float*)d_in[1];
    const float* e0_w1 = (const float*)d_in[2];
    const float* e0_b1 = (const float*)d_in[3];
    const float* e0_w2 = (const float*)d_in[4];
    const float* e0_b2 = (const float*)d_in[5];
    const float* e1_w1 = (const float*)d_in[6];
    const float* e1_b1 = (const float*)d_in[7];
    const float* e1_w2 = (const float*)d_in[8];
    const float* e1_b2 = (const float*)d_in[9];
    const float* nd_w1 = (const float*)d_in[10];
    const float* nd_b1 = (const float*)d_in[11];
    const float* nd_w2 = (const float*)d_in[12];
    const float* nd_b2 = (const float*)d_in[13];
    float* out = (float*)d_out;

    prepass_kernel<<<BATCH * 4, 128>>>(node_states, e0_w1, e0_b1, e1_w1, e1_b1);
    graphconv_main_kernel<<<BATCH * 32, 128>>>(
        node_states, edge_types,
        e0_w2, e0_b2, e1_w2, e1_b2,
        nd_w1, nd_b1, nd_w2, nd_b2,
        out);
}

// round 17
// speedup vs baseline: 1.0091x; 1.0091x over previous
#include <cuda_runtime.h>

#define N_AGENTS 64
#define N_EDGES  4032
#define D_NODE   16
#define HDIM     64
#define D_OUT    16
#define BATCH    128

// ---------------------------------------------------------------------------
// f32x2 packed-FMA helpers (sm_103a FFMA2 path; ptxas only emits via PTX)
// ---------------------------------------------------------------------------
__device__ __forceinline__ unsigned long long pack_f32x2(float lo, float hi) {
    unsigned long long r;
    asm("mov.b64 %0, {%1, %2};" : "=l"(r) : "f"(lo), "f"(hi));
    return r;
}
#define FMA_F32X2(d, a, b, c) \
    asm("fma.rn.f32x2 %0, %1, %2, %3;" : "=l"(d) : "l"(a), "l"(b), "l"(c))
#define UNPACK_F32X2(lo, hi, in) \
    asm("mov.b64 {%0, %1}, %2;" : "=f"(lo), "=f"(hi) : "l"(in))

// Per-node first-layer projections for both edge encoders.
// Layout: [b][n][enc*64 + h]  (128 floats per node) -> 4 MB each.
__device__ float g_PT[BATCH * N_AGENTS * 2 * HDIM];  // sender-half proj
__device__ float g_PB[BATCH * N_AGENTS * 2 * HDIM];  // receiver-half proj + b1

// ---------------------------------------------------------------------------
// Prepass: PT[b,n,enc,h] = sum_k x[b,n,k] * W1[enc][k][h]
//          PB[b,n,enc,h] = sum_k x[b,n,k] * W1[enc][16+k][h] + b1[enc][h]
// ---------------------------------------------------------------------------
__global__ void __launch_bounds__(128) prepass_kernel(
    const float* __restrict__ x,
    const float* __restrict__ e0_w1, const float* __restrict__ e0_b1,
    const float* __restrict__ e1_w1, const float* __restrict__ e1_b1)
{
    __shared__ float w1s[2][32][64];   // 16 KB
    __shared__ float b1s[2][64];
    __shared__ float xs[16][16];

    const int t = threadIdx.x;
    for (int i = t; i < 32 * 64; i += 128) {
        w1s[0][i >> 6][i & 63] = e0_w1[i];
        w1s[1][i >> 6][i & 63] = e1_w1[i];
    }
    if (t < 64) { b1s[0][t] = e0_b1[t]; b1s[1][t] = e1_b1[t]; }

    const int b  = blockIdx.x >> 2;
    const int n0 = (blockIdx.x & 3) * 16;
    for (int i = t; i < 256; i += 128)
        xs[i >> 4][i & 15] = x[(b * N_AGENTS + n0 + (i >> 4)) * D_NODE + (i & 15)];
    __syncthreads();

    const int enc = t >> 6;
    const int h   = t & 63;
    for (int nn = 0; nn < 16; nn++) {
        float pt = 0.f;
        float pb = b1s[enc][h];
        #pragma unroll
        for (int k = 0; k < 16; k++) {
            const float xv = xs[nn][k];
            pt += xv * w1s[enc][k][h];
            pb += xv * w1s[enc][16 + k][h];
        }
        const int n = n0 + nn;
        g_PT[(b * N_AGENTS + n) * 128 + t] = pt;
        g_PB[(b * N_AGENTS + n) * 128 + t] = pb;
    }
}

// ---------------------------------------------------------------------------
// Main fused kernel: one CTA per (batch b, receiver PAIR {r0, r0+1}).
// BARRIER-FREE mainloop: warp w = (rv, enc) produces exactly the h1 range it
// consumes — lane l computes cols c0 = enc*64+l and c1 = c0+32 of receiver
// rv's hidden vector, writes them to the warp's PRIVATE smem slab, then
// __syncwarp() only. No cross-warp coupling for all 64 sender iterations.
// Self-edge killed via tw=0 (exact).  Per-thread W2 columns l and l+32
// packed as f32x2 (fma.rn.f32x2 = 2 MACs/instr).
// Edge index for (s -> r): e = s*63 + (r < s ? r : r-1)
// ---------------------------------------------------------------------------
__global__ void __launch_bounds__(128) graphconv_main_kernel(
    const float* __restrict__ x,
    const float* __restrict__ edge_types,
    const float* __restrict__ e0_w2, const float* __restrict__ e0_b2,
    const float* __restrict__ e1_w2, const float* __restrict__ e1_b2,
    const float* __restrict__ nd_w1, const float* __restrict__ nd_b1,
    const float* __restrict__ nd_w2, const float* __restrict__ nd_b2,
    float* __restrict__ out)
{
    const int t    = threadIdx.x;
    const int w    = t >> 5;           // warp id 0..3
    const int l    = t & 31;           // lane
    const int rv   = w >> 1;           // receiver of the pair
    const int enc  = w & 1;            // encoder
    const int b    = blockIdx.x >> 5;
    const int pair = blockIdx.x & 31;
    const int r0   = pair * 2;
    const int r    = r0 + rv;

    __shared__ __align__(16) float h1w[4][2][64];   // [warp][buf][col] private slabs
    __shared__ float tws[2][64][2];                 // [rv][sender][enc]
    __shared__ float xs[2][16];                     // node_states rows
    __shared__ float accs[2][2][64];                // [rv][enc][h]
    __shared__ float hds[2][64];

    // --- per-thread W2 columns (l, l+32), packed as f32x2 pairs ---
    const float* __restrict__ w2g = (enc == 0) ? e0_w2 : e1_w2;
    unsigned long long wp0[32], wp1[32];
    #pragma unroll
    for (int j = 0; j < 32; j++) {
        wp0[j] = pack_f32x2(w2g[(2 * j) * 64 + l],      w2g[(2 * j + 1) * 64 + l]);
        wp1[j] = pack_f32x2(w2g[(2 * j) * 64 + l + 32], w2g[(2 * j + 1) * 64 + l + 32]);
    }
    const float* __restrict__ b2g = (enc == 0) ? e0_b2 : e1_b2;
    const float bias0 = b2g[l];
    const float bias1 = b2g[l + 32];

    // --- per-lane h1 production columns and receiver projection ---
    const int c0 = enc * 64 + l;
    const int c1 = c0 + 32;
    const float pbA = g_PB[(b * N_AGENTS + r) * 128 + c0];
    const float pbB = g_PB[(b * N_AGENTS + r) * 128 + c1];

    // type weights: 256 values, 2 per thread. tw=0 for self edge.
    for (int i = t; i < 256; i += 128) {
        const int trv = i >> 7;
        const int s   = (i >> 1) & 63;
        const int te  = i & 1;
        const int rr  = r0 + trv;
        float v = 0.f;
        if (s != rr) {
            const int e = s * 63 + (rr < s ? rr : rr - 1);
            v = edge_types[((long)b * N_EDGES + e) * 3 + 1 + te];
        }
        tws[trv][s][te] = v;
    }
    if (t < 32) xs[t >> 4][t & 15] = x[(b * N_AGENTS + r0 + (t >> 4)) * D_NODE + (t & 15)];
    __syncthreads();   // only barrier before the mainloop (tws/xs visibility)

    float acc0 = 0.f, acc1 = 0.f;
    float ptA = g_PT[(b * N_AGENTS + 0) * 128 + c0];   // prefetch sender 0
    float ptB = g_PT[(b * N_AGENTS + 0) * 128 + c1];

    for (int s = 0; s < 64; s++) {
        const int buf = s & 1;
        // producer: this warp's own h1 range for its receiver
        float a0 = ptA + pbA;
        float a1 = ptB + pbB;
        h1w[w][buf][l]      = a0 > 0.f ? a0 : 0.f;
        h1w[w][buf][l + 32] = a1 > 0.f ? a1 : 0.f;
        if (s + 1 < 64) {
            ptA = g_PT[(b * N_AGENTS + s + 1) * 128 + c0];
            ptB = g_PT[(b * N_AGENTS + s + 1) * 128 + c1];
        }
        __syncwarp();

        // consumer: dot of the warp-private h1 slab with 2 weight columns
        const ulonglong2* __restrict__ hv = (const ulonglong2*)&h1w[w][buf][0];
        unsigned long long d0 = 0ULL, d1 = 0ULL;
        #pragma unroll
        for (int j4 = 0; j4 < 16; j4++) {
            const ulonglong2 p = hv[j4];
            FMA_F32X2(d0, p.x, wp0[2 * j4],     d0);
            FMA_F32X2(d0, p.y, wp0[2 * j4 + 1], d0);
            FMA_F32X2(d1, p.x, wp1[2 * j4],     d1);
            FMA_F32X2(d1, p.y, wp1[2 * j4 + 1], d1);
        }
        float l0, u0, l1, u1;
        UNPACK_F32X2(l0, u0, d0);
        UNPACK_F32X2(l1, u1, d1);
        const float tw = tws[rv][s][enc];
        float eo0 = l0 + u0 + bias0;
        float eo1 = l1 + u1 + bias1;
        eo0 = eo0 > 0.f ? eo0 : 0.f;
        eo1 = eo1 > 0.f ? eo1 : 0.f;
        acc0 = fmaf(tw, eo0, acc0);
        acc1 = fmaf(tw, eo1, acc1);
    }

    accs[rv][enc][l]      = acc0;
    accs[rv][enc][l + 32] = acc1;
    __syncthreads();

    // --- decoder layer 1: hd[drv][hcol] = relu(b1 + [x, msg] @ nd_w1) ---
    {
        const int drv  = t >> 6;
        const int hcol = t & 63;
        float hd = nd_b1[hcol];
        #pragma unroll
        for (int k = 0; k < 16; k++)
            hd = fmaf(xs[drv][k], nd_w1[k * 64 + hcol], hd);
        #pragma unroll
        for (int k = 0; k < 64; k++) {
            const float m = accs[drv][0][k] + accs[drv][1][k];
            hd = fmaf(m, nd_w1[(16 + k) * 64 + hcol], hd);
        }
        hds[drv][hcol] = hd > 0.f ? hd : 0.f;
    }
    __syncthreads();

    // --- decoder layer 2: out[orv][o] = relu(b2 + hd @ nd_w2) ---
    if (t < 32) {
        const int orv = t >> 4;
        const int o   = t & 15;
        float v = nd_b2[o];
        #pragma unroll
        for (int j = 0; j < 64; j++)
            v = fmaf(hds[orv][j], nd_w2[j * 16 + o], v);
        out[(b * N_AGENTS + r0 + orv) * D_OUT + o] = v > 0.f ? v : 0.f;
    }
}

// ---------------------------------------------------------------------------
extern "C" void kernel_launch(void* const* d_in, const int* in_sizes, int n_in,
                              void* d_out, int out_size)
{
    const float* node_states = (const float*)d_in[0];
    const float* edge_types  = (const float*)d_in[1];
    const float* e0_w1 = (const float*)d_in[2];
    const float* e0_b1 = (const float*)d_in[3];
    const float* e0_w2 = (const float*)d_in[4];
    const float* e0_b2 = (const float*)d_in[5];
    const float* e1_w1 = (const float*)d_in[6];
    const float* e1_b1 = (const float*)d_in[7];
    const float* e1_w2 = (const float*)d_in[8];
    const float* e1_b2 = (const float*)d_in[9];
    const float* nd_w1 = (const float*)d_in[10];
    const float* nd_b1 = (const float*)d_in[11];
    const float* nd_w2 = (const float*)d_in[12];
    const float* nd_b2 = (const float*)d_in[13];
    float* out = (float*)d_out;

    prepass_kernel<<<BATCH * 4, 128>>>(node_states, e0_w1, e0_b1, e1_w1, e1_b1);
    graphconv_main_kernel<<<BATCH * 32, 128>>>(
        node_states, edge_types,
        e0_w2, e0_b2, e1_w2, e1_b2,
        nd_w1, nd_b1, nd_w2, nd_b2,
        out);
}